// round 6
// baseline (speedup 1.0000x reference)
#include <cuda_runtime.h>
#include <cuda_fp16.h>
#include <mma.h>
#include <stdint.h>

using namespace nvcuda;

#define NN 50000
#define EE 800000
#define HH 128
#define CC 10
#define LL 3
#define OO 2
#define KHOP 10
#define GG 128
#define NH ((size_t)NN * HH)
#define NB ((size_t)NN * 128)               // bytes per int8 z slot
#define Z8S ((size_t)(KHOP + 1) * NB)       // int8 z history per order
#define SCS ((size_t)(KHOP + 1) * NN)       // scales per order

// ---------------- scratch ----------------
__device__ __half  g_x16[NH];
__device__ int8_t  g_z8[OO * Z8S];
__device__ float   g_zsc[OO * SCS];
__device__ __half  g_xcat16[(size_t)NN * 256];
__device__ __half  g_t16[NH];
__device__ __half  g_h16[NH];
__device__ __half  g_win16[LL * OO * HH * HH];
__device__ __half  g_wfold16[LL * 256 * HH];
__device__ float   g_bfold[LL * HH];
__device__ __half  g_wn216[LL * HH * HH];
__device__ int     g_rowptr[OO * (NN + 1)];
__device__ int     g_cursor[OO * NN];
__device__ int     g_csrc[OO * EE];
__device__ float   g_cw[OO * EE];
__device__ float   g_pool[GG * HH];
__device__ float   g_p1[GG * HH];

// ---------------- CSR build ----------------
__global__ void csr_count(const int* __restrict__ dst, int* __restrict__ cnt) {
    int e = blockIdx.x * blockDim.x + threadIdx.x;
    if (e < EE) atomicAdd(&cnt[dst[e]], 1);
}

__global__ void csr_scan(const int* __restrict__ cnt, int* __restrict__ rowptr) {
    __shared__ int sdata[1024];
    __shared__ int sbase;
    int t = threadIdx.x;
    if (t == 0) { rowptr[0] = 0; sbase = 0; }
    __syncthreads();
    for (int c = 0; c < NN; c += 1024) {
        int v = (c + t < NN) ? cnt[c + t] : 0;
        sdata[t] = v;
        __syncthreads();
        for (int off = 1; off < 1024; off <<= 1) {
            int add = (t >= off) ? sdata[t - off] : 0;
            __syncthreads();
            sdata[t] += add;
            __syncthreads();
        }
        if (c + t < NN) rowptr[c + t + 1] = sbase + sdata[t];
        __syncthreads();
        if (t == 0) sbase += sdata[1023];
        __syncthreads();
    }
}

__global__ void csr_fill(const int* __restrict__ dst, const int* __restrict__ src,
                         const float* __restrict__ w,
                         int* __restrict__ cursor,
                         int* __restrict__ csrc, float* __restrict__ cw) {
    int e = blockIdx.x * blockDim.x + threadIdx.x;
    if (e < EE) {
        int pos = atomicAdd(&cursor[dst[e]], 1);
        csrc[pos] = src[e];
        cw[pos]   = w[e];
    }
}

// ---------------- casts + weight prep ----------------
__global__ void cast_f2h(const float* __restrict__ src, __half* __restrict__ dst, int n) {
    int i = blockIdx.x * blockDim.x + threadIdx.x;
    int i4 = i * 4;
    if (i4 + 3 < n) {
        float4 v = *(const float4*)(src + i4);
        __half2 h0 = __floats2half2_rn(v.x, v.y);
        __half2 h1 = __floats2half2_rn(v.z, v.w);
        *(uint2*)(dst + i4) = make_uint2(*(uint32_t*)&h0, *(uint32_t*)&h1);
    } else {
        for (int j = i4; j < n; j++) dst[j] = __float2half(src[j]);
    }
}

__global__ void fold_w(const float* __restrict__ Wout, const float* __restrict__ Wn1,
                       __half* __restrict__ Wfold) {
    int l = blockIdx.y;
    int idx = blockIdx.x * blockDim.x + threadIdx.x;
    if (idx >= 256 * 128) return;
    int k = idx >> 7, j = idx & 127;
    const float* wo = Wout + (size_t)l * 256 * 128 + (size_t)k * 128;
    const float* wn = Wn1 + (size_t)l * 128 * 128 + j;
    float acc = 0.f;
#pragma unroll 8
    for (int m = 0; m < 128; m++) acc = fmaf(wo[m], wn[(size_t)m * 128], acc);
    Wfold[(size_t)l * 256 * 128 + idx] = __float2half(acc);
}

__global__ void fold_b(const float* __restrict__ b_out, const float* __restrict__ Wn1,
                       const float* __restrict__ bn1, float* __restrict__ bf) {
    int l = blockIdx.y;
    int j = threadIdx.x;
    const float* bo = b_out + (size_t)l * 128;
    const float* wn = Wn1 + (size_t)l * 128 * 128 + j;
    float acc = bn1[(size_t)l * 128 + j];
    for (int m = 0; m < 128; m++) acc = fmaf(bo[m], wn[(size_t)m * 128], acc);
    bf[(size_t)l * 128 + j] = acc;
}

// ---------------- wmma fp16 GEMM; fp16 out OR int8+scale out (multi-order via blockIdx.y) ----------------
__global__ __launch_bounds__(256) void gemm16(
    const __half* __restrict__ A, int K, int lda,
    const __half* __restrict__ Bb, size_t Bstride,
    const float* __restrict__ biasb, size_t biasStride,
    __half* __restrict__ outb, size_t outStride,
    int8_t* __restrict__ out8b, size_t out8Stride,      // bytes
    float* __restrict__ oscb, size_t oscStride,
    const float* __restrict__ gam, const float* __restrict__ bet)
{
    extern __shared__ char smem[];
    __half* As = (__half*)smem;               // [128][136]
    __half* Bs = (__half*)(smem + 128 * 136 * 2);
    float*  Cs = (float*)smem;                // [128][132] (reused)

    const int o = blockIdx.y;
    const __half* B = Bb + (size_t)o * Bstride;
    const float* bias = biasb + (size_t)o * biasStride;

    const int tid = threadIdx.x;
    const int warp = tid >> 5;
    const int warpM = warp >> 1;
    const int warpN = warp & 1;
    const int rowBase = blockIdx.x * 128;

    wmma::fragment<wmma::accumulator, 16, 16, 16, float> acc[2][4];
#pragma unroll
    for (int i = 0; i < 2; i++)
#pragma unroll
        for (int j = 0; j < 4; j++) wmma::fill_fragment(acc[i][j], 0.f);

    const int nchunk = K >> 7;
    for (int kc = 0; kc < nchunk; kc++) {
#pragma unroll
        for (int it = 0; it < 8; it++) {
            int idx = it * 256 + tid;
            int r = idx >> 4;
            int c8 = (idx & 15) * 8;
            int grow = rowBase + r;
            uint4 av = make_uint4(0, 0, 0, 0);
            if (grow < NN) av = *(const uint4*)(A + (size_t)grow * lda + kc * 128 + c8);
            *(uint4*)(As + r * 136 + c8) = av;
            uint4 bv = *(const uint4*)(B + (size_t)(kc * 128 + r) * 128 + c8);
            *(uint4*)(Bs + r * 136 + c8) = bv;
        }
        __syncthreads();
#pragma unroll
        for (int ks = 0; ks < 8; ks++) {
            int k0 = ks * 16;
            wmma::fragment<wmma::matrix_a, 16, 16, 16, __half, wmma::row_major> af[2];
            wmma::fragment<wmma::matrix_b, 16, 16, 16, __half, wmma::row_major> bf[4];
#pragma unroll
            for (int i = 0; i < 2; i++)
                wmma::load_matrix_sync(af[i], As + (warpM * 32 + i * 16) * 136 + k0, 136);
#pragma unroll
            for (int j = 0; j < 4; j++)
                wmma::load_matrix_sync(bf[j], Bs + k0 * 136 + warpN * 64 + j * 16, 136);
#pragma unroll
            for (int i = 0; i < 2; i++)
#pragma unroll
                for (int j = 0; j < 4; j++)
                    wmma::mma_sync(acc[i][j], af[i], bf[j], acc[i][j]);
        }
        __syncthreads();
    }

#pragma unroll
    for (int i = 0; i < 2; i++)
#pragma unroll
        for (int j = 0; j < 4; j++)
            wmma::store_matrix_sync(Cs + (warpM * 32 + i * 16) * 132 + warpN * 64 + j * 16,
                                    acc[i][j], 132, wmma::mem_row_major);
    __syncthreads();

    const float RS = 0.9999950000374997f;  // 1/sqrt(1+1e-5)
    const int r = tid >> 1;
    const int cb0 = (tid & 1) * 64;
    const int grow = rowBase + r;
    if (grow >= NN) return;

    if (out8b) {
        // pass 1: apply bias, write back to Cs, track |max|
        int8_t* out8 = out8b + (size_t)o * out8Stride;
        float* osc = oscb + (size_t)o * oscStride;
        float m = 0.f;
#pragma unroll
        for (int j = 0; j < 16; j++) {
            int c0 = cb0 + j * 4;
            float4 v = *(const float4*)(Cs + r * 132 + c0);
            v.x += bias[c0]; v.y += bias[c0 + 1]; v.z += bias[c0 + 2]; v.w += bias[c0 + 3];
            m = fmaxf(m, fmaxf(fmaxf(fabsf(v.x), fabsf(v.y)), fmaxf(fabsf(v.z), fabsf(v.w))));
            *(float4*)(Cs + r * 132 + c0) = v;
        }
        m = fmaxf(m, __shfl_xor_sync(0xFFFFFFFF, m, 1));
        float inv = (m > 0.f) ? 127.f / m : 0.f;
        if ((tid & 1) == 0) osc[grow] = m * (1.f / 127.f);
#pragma unroll
        for (int j2 = 0; j2 < 4; j2++) {
            int c0 = cb0 + j2 * 16;
            uint32_t pk[4];
#pragma unroll
            for (int q = 0; q < 4; q++) {
                float4 v = *(const float4*)(Cs + r * 132 + c0 + q * 4);
                int a0 = __float2int_rn(v.x * inv), a1 = __float2int_rn(v.y * inv);
                int a2 = __float2int_rn(v.z * inv), a3 = __float2int_rn(v.w * inv);
                pk[q] = (uint32_t)(a0 & 0xFF) | ((uint32_t)(a1 & 0xFF) << 8) |
                        ((uint32_t)(a2 & 0xFF) << 16) | ((uint32_t)(a3 & 0xFF) << 24);
            }
            *(uint4*)(out8 + (size_t)grow * 128 + c0) = make_uint4(pk[0], pk[1], pk[2], pk[3]);
        }
    } else {
        __half* out = outb + (size_t)o * outStride;
#pragma unroll
        for (int j = 0; j < 8; j++) {
            int c0 = cb0 + j * 8;
            float4 v0 = *(const float4*)(Cs + r * 132 + c0);
            float4 v1 = *(const float4*)(Cs + r * 132 + c0 + 4);
            float t[8] = {v0.x, v0.y, v0.z, v0.w, v1.x, v1.y, v1.z, v1.w};
#pragma unroll
            for (int q = 0; q < 8; q++) {
                int c = c0 + q;
                t[q] += bias[c];
                if (gam) t[q] = fmaxf(t[q] * gam[c] * RS + bet[c], 0.f);
            }
            __half2 h0 = __floats2half2_rn(t[0], t[1]);
            __half2 h1 = __floats2half2_rn(t[2], t[3]);
            __half2 h2 = __floats2half2_rn(t[4], t[5]);
            __half2 h3 = __floats2half2_rn(t[6], t[7]);
            *(uint4*)(out + (size_t)grow * 128 + c0) =
                make_uint4(*(uint32_t*)&h0, *(uint32_t*)&h1, *(uint32_t*)&h2, *(uint32_t*)&h3);
        }
    }
}

// ---------------- SpMM hop (int8 z + row scale), dual order via blockIdx.y ----------------
__global__ __launch_bounds__(256) void spmm_hop8(
    const int* __restrict__ rowptrB,
    const int* __restrict__ csrcB,
    const float* __restrict__ cwB,
    int8_t* __restrict__ z8B,
    float* __restrict__ zscB,
    int k)
{
    const int o = blockIdx.y;
    const int* rowptr = rowptrB + (size_t)o * (NN + 1);
    const int* csrc = csrcB + (size_t)o * EE;
    const float* cw = cwB + (size_t)o * EE;
    const int8_t* zin = z8B + (size_t)o * Z8S + (size_t)k * NB;
    int8_t* zout = z8B + (size_t)o * Z8S + (size_t)(k + 1) * NB;
    const float* sin = zscB + (size_t)o * SCS + (size_t)k * NN;
    float* sout = zscB + (size_t)o * SCS + (size_t)(k + 1) * NN;

    int warp = (blockIdx.x * blockDim.x + threadIdx.x) >> 5;
    int lane = threadIdx.x & 31;
    if (warp >= NN) return;
    int beg = rowptr[warp], end = rowptr[warp + 1];

    float ax = 0.f, ay = 0.f, az = 0.f, aw = 0.f;
    int e = beg;
    for (; e + 4 <= end; e += 4) {
        int s0 = csrc[e], s1 = csrc[e + 1], s2 = csrc[e + 2], s3 = csrc[e + 3];
        float w0 = cw[e] * sin[s0];
        float w1 = cw[e + 1] * sin[s1];
        float w2 = cw[e + 2] * sin[s2];
        float w3 = cw[e + 3] * sin[s3];
        char4 c0 = *(const char4*)(zin + (size_t)s0 * 128 + lane * 4);
        char4 c1 = *(const char4*)(zin + (size_t)s1 * 128 + lane * 4);
        char4 c2 = *(const char4*)(zin + (size_t)s2 * 128 + lane * 4);
        char4 c3 = *(const char4*)(zin + (size_t)s3 * 128 + lane * 4);
        ax = fmaf(w0, (float)c0.x, fmaf(w1, (float)c1.x, fmaf(w2, (float)c2.x, fmaf(w3, (float)c3.x, ax))));
        ay = fmaf(w0, (float)c0.y, fmaf(w1, (float)c1.y, fmaf(w2, (float)c2.y, fmaf(w3, (float)c3.y, ay))));
        az = fmaf(w0, (float)c0.z, fmaf(w1, (float)c1.z, fmaf(w2, (float)c2.z, fmaf(w3, (float)c3.z, az))));
        aw = fmaf(w0, (float)c0.w, fmaf(w1, (float)c1.w, fmaf(w2, (float)c2.w, fmaf(w3, (float)c3.w, aw))));
    }
    for (; e < end; ++e) {
        int s = csrc[e];
        float w = cw[e] * sin[s];
        char4 c = *(const char4*)(zin + (size_t)s * 128 + lane * 4);
        ax = fmaf(w, (float)c.x, ax); ay = fmaf(w, (float)c.y, ay);
        az = fmaf(w, (float)c.z, az); aw = fmaf(w, (float)c.w, aw);
    }

    // row max over 128 values (warp reduce)
    float m = fmaxf(fmaxf(fabsf(ax), fabsf(ay)), fmaxf(fabsf(az), fabsf(aw)));
#pragma unroll
    for (int off = 16; off > 0; off >>= 1)
        m = fmaxf(m, __shfl_xor_sync(0xFFFFFFFF, m, off));
    float inv = (m > 0.f) ? 127.f / m : 0.f;
    if (lane == 0) sout[warp] = m * (1.f / 127.f);

    int q0 = __float2int_rn(ax * inv), q1 = __float2int_rn(ay * inv);
    int q2 = __float2int_rn(az * inv), q3 = __float2int_rn(aw * inv);
    uint32_t pk = (uint32_t)(q0 & 0xFF) | ((uint32_t)(q1 & 0xFF) << 8) |
                  ((uint32_t)(q2 & 0xFF) << 16) | ((uint32_t)(q3 & 0xFF) << 24);
    *(uint32_t*)(zout + (size_t)warp * 128 + lane * 4) = pk;
}

// ---------------- combine (warp per row, dual order): xcat[n, o*128+c] = sum_k fW[k]*sc[k,n]*z8[k,n,c] ----------------
__global__ __launch_bounds__(256) void combine8(
    const int8_t* __restrict__ z8B,
    const float* __restrict__ zscB,
    const float* __restrict__ fWl,
    __half* __restrict__ xcat)
{
    const int o = blockIdx.y;
    const int8_t* z8 = z8B + (size_t)o * Z8S;
    const float* zsc = zscB + (size_t)o * SCS;
    const float* fw = fWl + (size_t)o * (KHOP + 1);

    int warp = (blockIdx.x * blockDim.x + threadIdx.x) >> 5;
    int lane = threadIdx.x & 31;
    if (warp >= NN) return;

    float f0 = 0.f, f1 = 0.f, f2 = 0.f, f3 = 0.f;
#pragma unroll
    for (int k = 0; k <= KHOP; k++) {
        float f = fw[k] * zsc[(size_t)k * NN + warp];
        char4 c = *(const char4*)(z8 + (size_t)k * NB + (size_t)warp * 128 + lane * 4);
        f0 = fmaf(f, (float)c.x, f0); f1 = fmaf(f, (float)c.y, f1);
        f2 = fmaf(f, (float)c.z, f2); f3 = fmaf(f, (float)c.w, f3);
    }
    __half2 h0 = __floats2half2_rn(f0, f1);
    __half2 h1 = __floats2half2_rn(f2, f3);
    *(uint2*)(xcat + (size_t)warp * 256 + (size_t)o * 128 + lane * 4) =
        make_uint2(*(uint32_t*)&h0, *(uint32_t*)&h1);
}

// ---------------- pooling + head ----------------
__global__ void pool_kernel(const __half* __restrict__ h, const int* __restrict__ batch,
                            float* __restrict__ p) {
    int idx = blockIdx.x * blockDim.x + threadIdx.x;
    if (idx >= NN * HH) return;
    int node = idx >> 7;
    int f = idx & 127;
    atomicAdd(&p[batch[node] * HH + f], __half2float(h[idx]));
}

__global__ void head1(const float* __restrict__ p, const float* __restrict__ W1,
                      const float* __restrict__ b1, float* __restrict__ p1) {
    int i = blockIdx.x * blockDim.x + threadIdx.x;
    if (i >= GG * HH) return;
    int g = i >> 7, j = i & 127;
    float acc = b1[j];
    for (int k = 0; k < HH; k++)
        acc = fmaf(p[g * HH + k], W1[k * HH + j], acc);
    p1[i] = fmaxf(acc, 0.f);
}

__global__ void head2(const float* __restrict__ p1, const float* __restrict__ W2,
                      const float* __restrict__ b2, float* __restrict__ outp) {
    int i = blockIdx.x * blockDim.x + threadIdx.x;
    if (i >= GG * CC) return;
    int g = i / CC, j = i % CC;
    float acc = b2[j];
    for (int k = 0; k < HH; k++)
        acc = fmaf(p1[g * HH + k], W2[k * CC + j], acc);
    outp[i] = acc;
}

// ---------------- host orchestration ----------------
extern "C" void kernel_launch(void* const* d_in, const int* in_sizes, int n_in,
                              void* d_out, int out_size) {
    const float* x      = (const float*)d_in[0];
    const int*   eidx   = (const int*)  d_in[1];
    const float* ew     = (const float*)d_in[2];
    const int*   batch  = (const int*)  d_in[3];
    const float* W_in   = (const float*)d_in[4];
    const float* b_in   = (const float*)d_in[5];
    const float* fW     = (const float*)d_in[6];
    const float* W_out  = (const float*)d_in[7];
    const float* b_out  = (const float*)d_in[8];
    const float* Wn1    = (const float*)d_in[9];
    const float* bn1    = (const float*)d_in[10];
    const float* g1     = (const float*)d_in[11];
    const float* be1    = (const float*)d_in[12];
    const float* Wn2    = (const float*)d_in[13];
    const float* bn2    = (const float*)d_in[14];
    const float* g2     = (const float*)d_in[15];
    const float* be2    = (const float*)d_in[16];
    const float* W1     = (const float*)d_in[17];
    const float* b1     = (const float*)d_in[18];
    const float* W2     = (const float*)d_in[19];
    const float* b2     = (const float*)d_in[20];
    float* outp = (float*)d_out;

    __half *x16, *xcat16, *t16, *h16, *win16, *wfold16, *wn216;
    int8_t *z8;
    float *zsc, *bfold, *pool, *p1, *cw;
    int *rowptr, *cursor, *csrc;
    cudaGetSymbolAddress((void**)&x16, g_x16);
    cudaGetSymbolAddress((void**)&z8, g_z8);
    cudaGetSymbolAddress((void**)&zsc, g_zsc);
    cudaGetSymbolAddress((void**)&xcat16, g_xcat16);
    cudaGetSymbolAddress((void**)&t16, g_t16);
    cudaGetSymbolAddress((void**)&h16, g_h16);
    cudaGetSymbolAddress((void**)&win16, g_win16);
    cudaGetSymbolAddress((void**)&wfold16, g_wfold16);
    cudaGetSymbolAddress((void**)&bfold, g_bfold);
    cudaGetSymbolAddress((void**)&wn216, g_wn216);
    cudaGetSymbolAddress((void**)&pool, g_pool);
    cudaGetSymbolAddress((void**)&p1, g_p1);
    cudaGetSymbolAddress((void**)&rowptr, g_rowptr);
    cudaGetSymbolAddress((void**)&cursor, g_cursor);
    cudaGetSymbolAddress((void**)&csrc, g_csrc);
    cudaGetSymbolAddress((void**)&cw, g_cw);

    const size_t WIN_SZ = (size_t)LL * OO * HH * HH;
    const size_t WN_SZ  = (size_t)LL * HH * HH;
    const int EB = (EE + 255) / 256;
    const int MB = (NN + 127) / 128;
    const int SB = ((NN * 32) + 255) / 256;
    const int GEMM_SMEM = 128 * 136 * 2 * 2;

    cudaFuncSetAttribute(gemm16, cudaFuncAttributeMaxDynamicSharedMemorySize, GEMM_SMEM);

    // ---- weight prep ----
    cast_f2h<<<(int)((WIN_SZ / 4 + 255) / 256), 256>>>(W_in, win16, (int)WIN_SZ);
    cast_f2h<<<(int)((WN_SZ / 4 + 255) / 256), 256>>>(Wn2, wn216, (int)WN_SZ);
    cast_f2h<<<(int)((NH / 4 + 255) / 256), 256>>>(x, x16, (int)NH);
    {
        dim3 g((256 * 128 + 255) / 256, LL);
        fold_w<<<g, 256>>>(W_out, Wn1, wfold16);
        dim3 gb(1, LL);
        fold_b<<<gb, 128>>>(b_out, Wn1, bn1, bfold);
    }

    // ---- build CSR per order ----
    for (int o = 0; o < OO; o++) {
        const int* dst = eidx + (size_t)o * 2 * EE;
        const int* src = dst + EE;
        int* cnt = cursor + (size_t)o * NN;
        int* rp  = rowptr + (size_t)o * (NN + 1);
        cudaMemsetAsync(cnt, 0, NN * sizeof(int), 0);
        csr_count<<<EB, 256>>>(dst, cnt);
        csr_scan<<<1, 1024>>>(cnt, rp);
        cudaMemcpyAsync(cnt, rp, NN * sizeof(int), cudaMemcpyDeviceToDevice, 0);
        csr_fill<<<EB, 256>>>(dst, src, ew + (size_t)o * EE, cnt,
                              csrc + (size_t)o * EE, cw + (size_t)o * EE);
    }

    const __half* hin = x16;
    for (int l = 0; l < LL; l++) {
        // z0 (both orders): int8 + scale
        {
            dim3 g(MB, OO);
            gemm16<<<g, 256, GEMM_SMEM>>>(hin, 128, 128,
                                          win16 + (size_t)l * OO * HH * HH, (size_t)HH * HH,
                                          b_in + (size_t)l * OO * HH, HH,
                                          nullptr, 0,
                                          z8, Z8S, zsc, SCS,
                                          nullptr, nullptr);
        }
        for (int k = 0; k < KHOP; k++) {
            dim3 g(SB, OO);
            spmm_hop8<<<g, 256>>>(rowptr, csrc, cw, z8, zsc, k);
        }
        {
            dim3 g(SB, OO);
            combine8<<<g, 256>>>(z8, zsc, fW + (size_t)l * OO * (KHOP + 1), xcat16);
        }
        // t = relu(bn1(xcat @ Wfold + bfold))   [K=256]
        gemm16<<<dim3(MB, 1), 256, GEMM_SMEM>>>(xcat16, 256, 256,
                                      wfold16 + (size_t)l * 256 * HH, 0,
                                      bfold + (size_t)l * HH, 0,
                                      t16, 0,
                                      nullptr, 0, nullptr, 0,
                                      g1 + (size_t)l * HH, be1 + (size_t)l * HH);
        // h = relu(bn2(t @ Wn2 + bn2))
        gemm16<<<dim3(MB, 1), 256, GEMM_SMEM>>>(t16, 128, 128,
                                      wn216 + (size_t)l * HH * HH, 0,
                                      bn2 + (size_t)l * HH, 0,
                                      h16, 0,
                                      nullptr, 0, nullptr, 0,
                                      g2 + (size_t)l * HH, be2 + (size_t)l * HH);
        hin = h16;
    }

    cudaMemsetAsync(pool, 0, GG * HH * sizeof(float), 0);
    pool_kernel<<<(NN * HH + 255) / 256, 256>>>(h16, batch, pool);
    head1<<<(GG * HH + 255) / 256, 256>>>(pool, W1, b1, p1);
    head2<<<(GG * CC + 255) / 256, 256>>>(p1, W2, b2, outp);
}